// round 9
// baseline (speedup 1.0000x reference)
#include <cuda_runtime.h>
#include <cuda_fp16.h>
#include <cstdint>

// SelfAttention_82403242541160 — R9: 128x128 block tile, 4 warps, 64x64 warp tile
// (MMA/LDSM 4.0 like R7 but launch-safe: 128 thr, ~180 regs, 2 CTA/SM)
// out_b = (sum_n w_n x_n) @ Wv,  w_n = sum_q P_qn/Z_q,
// P = exp2(Qs K^T) with (1/16)*log2e folded into Qs, Z = rowsum(P).

#define BB 32
#define NN 2048
#define DD 256

__device__ __half g_Xh[(size_t)BB * NN * DD];
__device__ __half g_Wt[2 * DD * DD];            // Wq^T, Wk^T fp16 [512][256]
__device__ __half g_Qh[(size_t)BB * NN * DD];
__device__ __half g_Kh[(size_t)BB * NN * DD];
__device__ __half g_P [(size_t)BB * NN * NN];   // 256 MB
__device__ float g_Z [BB * NN];
__device__ float g_Wc[BB * NN];
__device__ float g_Y [BB * DD];

// ---------------------------------------------------------------------------
__device__ __forceinline__ uint32_t smem_u32(const void* p) {
    uint32_t a;
    asm("{ .reg .u64 t; cvta.to.shared.u64 t, %1; cvt.u32.u64 %0, t; }"
        : "=r"(a) : "l"(p));
    return a;
}
__device__ __forceinline__ void cp16(uint32_t s, const void* g) {
    asm volatile("cp.async.cg.shared.global [%0], [%1], 16;" :: "r"(s), "l"(g));
}
#define CP_COMMIT() asm volatile("cp.async.commit_group;" ::: "memory")
#define CP_WAIT(n)  asm volatile("cp.async.wait_group %0;" :: "n"(n) : "memory")

__device__ __forceinline__ void ldm_x4(uint32_t addr, uint32_t* r) {
    asm volatile("ldmatrix.sync.aligned.m8n8.x4.shared.b16 {%0,%1,%2,%3}, [%4];"
                 : "=r"(r[0]), "=r"(r[1]), "=r"(r[2]), "=r"(r[3]) : "r"(addr));
}
__device__ __forceinline__ void mma_16816(float* d, const uint32_t* a, const uint32_t* b) {
    asm volatile(
        "mma.sync.aligned.m16n8k16.row.col.f32.f16.f16.f32 "
        "{%0,%1,%2,%3}, {%4,%5,%6,%7}, {%8,%9}, {%0,%1,%2,%3};"
        : "+f"(d[0]), "+f"(d[1]), "+f"(d[2]), "+f"(d[3])
        : "r"(a[0]), "r"(a[1]), "r"(a[2]), "r"(a[3]), "r"(b[0]), "r"(b[1]));
}

// smem stage: A 128 rows x 64h (16 KB) + B 128 rows x 64h (16 KB) = 32 KB.
// 128 B/row; 16B units swizzled u ^= (row&7).
#define NT          128
#define STAGE_BYTES 32768
#define SMEM_DYN    (3 * STAGE_BYTES)

__device__ __forceinline__ void load_stage(
    uint32_t st, const __half* __restrict__ Ag, const __half* __restrict__ Bg,
    int k0, int tid) {
#pragma unroll
    for (int i = 0; i < 8; i++) {                 // A then B, 1024 units each
        int u_idx = tid + i * NT;
        int row = u_idx >> 3, u = u_idx & 7;
        uint32_t so = (uint32_t)((row << 7) + ((u ^ (row & 7)) << 4));
        cp16(st + so, Ag + (size_t)row * DD + k0 + u * 8);
        cp16(st + 16384 + so, Bg + (size_t)row * DD + k0 + u * 8);
    }
}

// Warp grid 2x2: wm=wid>>1 (64 rows), wn=wid&1 (64 cols). acc[4][8][4].
// Per chunk per warp: 16 A-LDSM + 16 B-LDSM -> 128 MMAs (ratio 4.0).
__device__ __forceinline__ void compute_stage(
    uint32_t smA, uint32_t smB, int wm, int wn, int lane, float acc[4][8][4]) {
    int arow = wm * 64 + (lane & 15);
    int ahalf = lane >> 4;
    int brow = wn * 64 + ((lane >> 4) << 3) + (lane & 7);
    int bhalf = (lane >> 3) & 1;
#pragma unroll
    for (int ks = 0; ks < 4; ks++) {
        uint32_t a[4][4];
#pragma unroll
        for (int mf = 0; mf < 4; mf++) {
            int r = arow + mf * 16;
            int u = ks * 2 + ahalf;
            ldm_x4(smA + (r << 7) + ((u ^ (r & 7)) << 4), a[mf]);
        }
        uint32_t b[8][2];
#pragma unroll
        for (int p = 0; p < 4; p++) {
            int r = brow + p * 16;
            int u = ks * 2 + bhalf;
            uint32_t t[4];
            ldm_x4(smB + (r << 7) + ((u ^ (r & 7)) << 4), t);
            b[p * 2][0] = t[0];     b[p * 2][1] = t[1];
            b[p * 2 + 1][0] = t[2]; b[p * 2 + 1][1] = t[3];
        }
#pragma unroll
        for (int mf = 0; mf < 4; mf++)
#pragma unroll
            for (int nf = 0; nf < 8; nf++)
                mma_16816(acc[mf][nf], a[mf], b[nf]);
    }
}

// 128x128x256 tile GEMM, 3-buffer pipeline, one syncthreads per K-chunk.
__device__ __forceinline__ void gemm_tile(
    const __half* __restrict__ Ag, const __half* __restrict__ Bg,
    char* dsm, int tid, float acc[4][8][4]) {
    uint32_t sm0 = smem_u32(dsm);
    int wid = tid >> 5, lane = tid & 31;
    int wm = wid >> 1, wn = wid & 1;

#pragma unroll
    for (int mf = 0; mf < 4; mf++)
#pragma unroll
        for (int nf = 0; nf < 8; nf++)
#pragma unroll
            for (int j = 0; j < 4; j++) acc[mf][nf][j] = 0.0f;

    load_stage(sm0, Ag, Bg, 0, tid);
    CP_COMMIT();
    load_stage(sm0 + STAGE_BYTES, Ag, Bg, 64, tid);
    CP_COMMIT();

#pragma unroll
    for (int it = 0; it < 4; it++) {
        if (it < 3) { CP_WAIT(1); } else { CP_WAIT(0); }
        __syncthreads();
        if (it < 2) {
            load_stage(sm0 + ((it + 2) % 3) * STAGE_BYTES, Ag, Bg, (it + 2) * 64, tid);
            CP_COMMIT();
        }
        uint32_t cs = sm0 + (it % 3) * STAGE_BYTES;
        compute_stage(cs, cs + 16384, wm, wn, lane, acc);
    }
}

// ---------------------------------------------------------------------------
__global__ void __launch_bounds__(256) init_kernel() {
    int i = blockIdx.x * 256 + threadIdx.x;
    if (i < BB * NN) { g_Z[i] = 0.0f; g_Wc[i] = 0.0f; }
    if (i < BB * DD) g_Y[i] = 0.0f;
}

__global__ void __launch_bounds__(256) x_kernel(const float* __restrict__ a,
                                                const float* __restrict__ b) {
    size_t i = (size_t)(blockIdx.x * 256 + threadIdx.x) * 8;
    float4 a0 = *(const float4*)(a + i), a1 = *(const float4*)(a + i + 4);
    float4 b0 = *(const float4*)(b + i), b1 = *(const float4*)(b + i + 4);
    __half2 p0 = __floats2half2_rn(a0.x + b0.x, a0.y + b0.y);
    __half2 p1 = __floats2half2_rn(a0.z + b0.z, a0.w + b0.w);
    __half2 p2 = __floats2half2_rn(a1.x + b1.x, a1.y + b1.y);
    __half2 p3 = __floats2half2_rn(a1.z + b1.z, a1.w + b1.w);
    uint4 u;
    u.x = *(unsigned*)&p0; u.y = *(unsigned*)&p1;
    u.z = *(unsigned*)&p2; u.w = *(unsigned*)&p3;
    *(uint4*)(g_Xh + i) = u;
}

__global__ void __launch_bounds__(256) wt_kernel(const float* __restrict__ wq,
                                                 const float* __restrict__ wk) {
    int i = blockIdx.x * 256 + threadIdx.x;   // m*65536 + n*256 + k
    int m = i >> 16, n = (i >> 8) & 255, k = i & 255;
    const float* w = (m == 0) ? wq : wk;
    g_Wt[i] = __float2half_rn(w[k * DD + n]);
}

// ---------------------------------------------------------------------------
// Q,K projections: grid (4, 512); ct = mat*2 + colhalf.  128 threads.
__global__ void __launch_bounds__(128) qk_proj_kernel() {
    extern __shared__ char dsm[];
    int tid = threadIdx.x, wid = tid >> 5, lane = tid & 31;
    int ct = blockIdx.x, mt = blockIdx.y;

    float acc[4][8][4];
    gemm_tile(g_Xh + (size_t)mt * 128 * DD, g_Wt + (size_t)ct * 128 * DD,
              dsm, tid, acc);

    int wm = wid >> 1, wn = wid & 1;
    int lr = lane >> 2, lc = (lane & 3) * 2;
    int mat = ct >> 1;
    int colbase = (ct & 1) * 128;
    const float QSCALE = 0.09016844f;  // (1/16)*log2(e)
    float sc = (mat == 0) ? QSCALE : 1.0f;
    __half* O = (mat == 0) ? g_Qh : g_Kh;

#pragma unroll
    for (int mf = 0; mf < 4; mf++) {
        size_t r0 = (size_t)mt * 128 + wm * 64 + mf * 16 + lr;
        size_t r1 = r0 + 8;
#pragma unroll
        for (int nf = 0; nf < 8; nf++) {
            int c = colbase + wn * 64 + nf * 8 + lc;
            __half2 v0 = __floats2half2_rn(acc[mf][nf][0] * sc, acc[mf][nf][1] * sc);
            __half2 v1 = __floats2half2_rn(acc[mf][nf][2] * sc, acc[mf][nf][3] * sc);
            *(__half2*)(O + r0 * DD + c) = v0;
            *(__half2*)(O + r1 * DD + c) = v1;
        }
    }
}

// ---------------------------------------------------------------------------
// Qs K^T -> exp2 -> P (fp16) + Z rowsum.  grid (16 nt, 16 qt, 32 b).  128 thr.
__global__ void __launch_bounds__(128) qk_mma_kernel() {
    extern __shared__ char dsm[];
    int tid = threadIdx.x, wid = tid >> 5, lane = tid & 31;
    int nt = blockIdx.x, qt = blockIdx.y, b = blockIdx.z;

    float acc[4][8][4];
    gemm_tile(g_Qh + ((size_t)b * NN + qt * 128) * DD,
              g_Kh + ((size_t)b * NN + nt * 128) * DD, dsm, tid, acc);

    int wm = wid >> 1, wn = wid & 1;
    int lr = lane >> 2, lc = (lane & 3) * 2;

#pragma unroll
    for (int mf = 0; mf < 4; mf++) {
        int q0 = qt * 128 + wm * 64 + mf * 16 + lr;
        int q1 = q0 + 8;
        float z0 = 0.0f, z1 = 0.0f;
#pragma unroll
        for (int nf = 0; nf < 8; nf++) {
            int c = nt * 128 + wn * 64 + nf * 8 + lc;
            __half2 p0 = h2exp2(__floats2half2_rn(acc[mf][nf][0], acc[mf][nf][1]));
            __half2 p1 = h2exp2(__floats2half2_rn(acc[mf][nf][2], acc[mf][nf][3]));
            *(__half2*)(g_P + ((size_t)b * NN + q0) * NN + c) = p0;
            *(__half2*)(g_P + ((size_t)b * NN + q1) * NN + c) = p1;
            float2 f0 = __half22float2(p0), f1 = __half22float2(p1);
            z0 += f0.x + f0.y;
            z1 += f1.x + f1.y;
        }
        z0 += __shfl_xor_sync(0xffffffffu, z0, 1);
        z0 += __shfl_xor_sync(0xffffffffu, z0, 2);
        z1 += __shfl_xor_sync(0xffffffffu, z1, 1);
        z1 += __shfl_xor_sync(0xffffffffu, z1, 2);
        if ((lane & 3) == 0) {
            atomicAdd(&g_Z[b * NN + q0], z0);
            atomicAdd(&g_Z[b * NN + q1], z1);
        }
    }
}

// ---------------------------------------------------------------------------
// w_n += sum over 128-q chunk of P/Z.  grid (16, 32); thread owns 8 n (uint4).
__global__ void __launch_bounds__(256) colsum_kernel() {
    __shared__ float rz[128];
    int b = blockIdx.y;
    int q0 = blockIdx.x * 128;
    int tid = threadIdx.x;

    if (tid < 128) rz[tid] = 1.0f / g_Z[b * NN + q0 + tid];
    __syncthreads();

    int n0 = tid * 8;
    float w[8];
#pragma unroll
    for (int j = 0; j < 8; j++) w[j] = 0.0f;

    const __half* Pb = g_P + ((size_t)b * NN + q0) * NN + n0;
#pragma unroll 4
    for (int q = 0; q < 128; q++) {
        uint4 u = *(const uint4*)(Pb + (size_t)q * NN);
        float rzq = rz[q];
        const __half2* h = (const __half2*)&u;
#pragma unroll
        for (int j = 0; j < 4; j++) {
            float2 f = __half22float2(h[j]);
            w[2 * j]     += f.x * rzq;
            w[2 * j + 1] += f.y * rzq;
        }
    }
#pragma unroll
    for (int j = 0; j < 8; j++)
        atomicAdd(&g_Wc[b * NN + n0 + j], w[j]);
}

// ---------------------------------------------------------------------------
// y[b,d] += sum over 256-n chunk of w_n * (td+ue)[b,n,d].  grid (8, 32).
__global__ void __launch_bounds__(256) y_kernel(const float* __restrict__ td,
                                                const float* __restrict__ ue) {
    __shared__ float ws[256];
    int b = blockIdx.y;
    int n0 = blockIdx.x * 256;
    ws[threadIdx.x] = g_Wc[b * NN + n0 + threadIdx.x];
    __syncthreads();

    int d = threadIdx.x;
    size_t base = ((size_t)b * NN + n0) * DD + d;
    float acc = 0.0f;
#pragma unroll 8
    for (int r = 0; r < 256; r++) {
        size_t idx = base + (size_t)r * DD;
        acc += ws[r] * (td[idx] + ue[idx]);
    }
    atomicAdd(&g_Y[b * DD + d], acc);
}

// ---------------------------------------------------------------------------
// out[b,k] = sum_d y[b,d] * wv[d,k].  grid 32, fp32 exact.
__global__ void __launch_bounds__(256) out_kernel(const float* __restrict__ wv,
                                                  float* __restrict__ out) {
    __shared__ float ys[DD];
    int b = blockIdx.x, k = threadIdx.x;
    ys[k] = g_Y[b * DD + k];
    __syncthreads();
    float acc = 0.0f;
#pragma unroll 8
    for (int d = 0; d < DD; d++)
        acc += ys[d] * wv[d * DD + k];
    out[b * DD + k] = acc;
}

// ---------------------------------------------------------------------------
extern "C" void kernel_launch(void* const* d_in, const int* in_sizes, int n_in,
                              void* d_out, int out_size) {
    const float* td = (const float*)d_in[0];
    const float* ue = (const float*)d_in[1];
    const float* wq = (const float*)d_in[2];
    const float* wk = (const float*)d_in[3];
    const float* wv = (const float*)d_in[4];
    float* out = (float*)d_out;

    cudaFuncSetAttribute(qk_proj_kernel,
                         cudaFuncAttributeMaxDynamicSharedMemorySize, SMEM_DYN);
    cudaFuncSetAttribute(qk_mma_kernel,
                         cudaFuncAttributeMaxDynamicSharedMemorySize, SMEM_DYN);

    init_kernel<<<(BB * NN) / 256, 256>>>();
    x_kernel<<<(size_t)BB * NN * DD / (256 * 8), 256>>>(td, ue);
    wt_kernel<<<2 * DD * DD / 256, 256>>>(wq, wk);
    qk_proj_kernel<<<dim3(4, (BB * NN) / 128), 128, SMEM_DYN>>>();
    qk_mma_kernel<<<dim3(NN / 128, NN / 128, BB), 128, SMEM_DYN>>>();
    colsum_kernel<<<dim3(NN / 128, BB), 256>>>();
    y_kernel<<<dim3(8, BB), 256>>>(td, ue);
    out_kernel<<<BB, 256>>>(wv, out);
}

// round 12
// speedup vs baseline: 1.0927x; 1.0927x over previous
#include <cuda_runtime.h>
#include <cuda_fp16.h>
#include <cstdint>

// SelfAttention_82403242541160 — R12: R11 with y_kernel index fix
// (R11 bug: 256 threads x half2 over a 128-half2 row -> OOB atomicAdd into
//  next batch's Y. Now two 128-thread groups each covering 128 n-rows.)
// out_b = (sum_n w_n x_n) @ Wv,  w_n = sum_q P_qn/Z_q,
// P = exp2(Qs K^T) with (1/16)*log2e folded into Qs, Z = rowsum(P).

#define BB 32
#define NN 2048
#define DD 256

__device__ __half g_Xh[(size_t)BB * NN * DD];
__device__ __half g_Wt[2 * DD * DD];            // Wq^T, Wk^T fp16 [512][256]
__device__ __half g_Qh[(size_t)BB * NN * DD];
__device__ __half g_Kh[(size_t)BB * NN * DD];
__device__ __half g_P [(size_t)BB * NN * NN];   // 256 MB fp16
__device__ float g_Z [BB * NN];
__device__ float g_Wc[BB * NN];
__device__ float g_Y [BB * DD];

// ---------------------------------------------------------------------------
__device__ __forceinline__ uint32_t smem_u32(const void* p) {
    uint32_t a;
    asm("{ .reg .u64 t; cvta.to.shared.u64 t, %1; cvt.u32.u64 %0, t; }"
        : "=r"(a) : "l"(p));
    return a;
}
__device__ __forceinline__ void cp16(uint32_t s, const void* g) {
    asm volatile("cp.async.cg.shared.global [%0], [%1], 16;" :: "r"(s), "l"(g));
}
#define CP_COMMIT() asm volatile("cp.async.commit_group;" ::: "memory")
#define CP_WAIT(n)  asm volatile("cp.async.wait_group %0;" :: "n"(n) : "memory")

__device__ __forceinline__ void ldm_x4(uint32_t addr, uint32_t* r) {
    asm volatile("ldmatrix.sync.aligned.m8n8.x4.shared.b16 {%0,%1,%2,%3}, [%4];"
                 : "=r"(r[0]), "=r"(r[1]), "=r"(r[2]), "=r"(r[3]) : "r"(addr));
}
__device__ __forceinline__ void mma_16816(float* d, const uint32_t* a, const uint32_t* b) {
    asm volatile(
        "mma.sync.aligned.m16n8k16.row.col.f32.f16.f16.f32 "
        "{%0,%1,%2,%3}, {%4,%5,%6,%7}, {%8,%9}, {%0,%1,%2,%3};"
        : "+f"(d[0]), "+f"(d[1]), "+f"(d[2]), "+f"(d[3])
        : "r"(a[0]), "r"(a[1]), "r"(a[2]), "r"(a[3]), "r"(b[0]), "r"(b[1]));
}

// smem stage: A(128x64h) + B(128x64h), 128 B/row, 16B units swizzled u ^= (row&7)
#define STAGE_BYTES 32768
#define SMEM_DYN    (3 * STAGE_BYTES)

__device__ __forceinline__ void load_stage(
    uint32_t st, const __half* __restrict__ Ag, const __half* __restrict__ Bg,
    int k0, int tid) {
#pragma unroll
    for (int i = 0; i < 4; i++) {
        int u_idx = tid + i * 256;            // 0..1023
        int row = u_idx >> 3, u = u_idx & 7;
        uint32_t so = (uint32_t)((row << 7) + ((u ^ (row & 7)) << 4));
        cp16(st + so, Ag + (size_t)row * DD + k0 + u * 8);
        cp16(st + 16384 + so, Bg + (size_t)row * DD + k0 + u * 8);
    }
}

// Warp grid 2x4 (R6 proven config): warp tile 64x32, acc[4][4][4].
__device__ __forceinline__ void compute_stage(
    uint32_t smA, uint32_t smB, int wm, int wn, int lane, float acc[4][4][4]) {
    int arow = wm * 64 + (lane & 15);
    int ahalf = lane >> 4;
    int brow = wn * 32 + ((lane >> 4) << 3) + (lane & 7);
    int bhalf = (lane >> 3) & 1;
#pragma unroll
    for (int ks = 0; ks < 4; ks++) {
        uint32_t a[4][4];
#pragma unroll
        for (int mf = 0; mf < 4; mf++) {
            int r = arow + mf * 16;
            int u = ks * 2 + ahalf;
            ldm_x4(smA + (r << 7) + ((u ^ (r & 7)) << 4), a[mf]);
        }
        uint32_t b[4][2];
#pragma unroll
        for (int p = 0; p < 2; p++) {
            int r = brow + p * 16;
            int u = ks * 2 + bhalf;
            uint32_t t[4];
            ldm_x4(smB + (r << 7) + ((u ^ (r & 7)) << 4), t);
            b[p * 2][0] = t[0];     b[p * 2][1] = t[1];
            b[p * 2 + 1][0] = t[2]; b[p * 2 + 1][1] = t[3];
        }
#pragma unroll
        for (int mf = 0; mf < 4; mf++)
#pragma unroll
            for (int nf = 0; nf < 4; nf++)
                mma_16816(acc[mf][nf], a[mf], b[nf]);
    }
}

// 128x128x256 tile GEMM, 3-buffer pipeline, one syncthreads per K-chunk.
__device__ __forceinline__ void gemm_tile(
    const __half* __restrict__ Ag, const __half* __restrict__ Bg,
    char* dsm, int tid, float acc[4][4][4]) {
    uint32_t sm0 = smem_u32(dsm);
    int wid = tid >> 5, lane = tid & 31;
    int wm = wid >> 2, wn = wid & 3;

#pragma unroll
    for (int mf = 0; mf < 4; mf++)
#pragma unroll
        for (int nf = 0; nf < 4; nf++)
#pragma unroll
            for (int j = 0; j < 4; j++) acc[mf][nf][j] = 0.0f;

    load_stage(sm0, Ag, Bg, 0, tid);
    CP_COMMIT();
    load_stage(sm0 + STAGE_BYTES, Ag, Bg, 64, tid);
    CP_COMMIT();

#pragma unroll
    for (int it = 0; it < 4; it++) {
        if (it < 3) { CP_WAIT(1); } else { CP_WAIT(0); }
        __syncthreads();
        if (it < 2) {
            load_stage(sm0 + ((it + 2) % 3) * STAGE_BYTES, Ag, Bg, (it + 2) * 64, tid);
            CP_COMMIT();
        }
        uint32_t cs = sm0 + (it % 3) * STAGE_BYTES;
        compute_stage(cs, cs + 16384, wm, wn, lane, acc);
    }
}

// ---------------------------------------------------------------------------
__global__ void __launch_bounds__(256) init_kernel() {
    int i = blockIdx.x * 256 + threadIdx.x;
    if (i < BB * NN) { g_Z[i] = 0.0f; g_Wc[i] = 0.0f; }
    if (i < BB * DD) g_Y[i] = 0.0f;
}

// prep: X = td+ue (fp16) everywhere; Wt transpose piggybacked on first blocks.
__global__ void __launch_bounds__(256) prep_kernel(const float* __restrict__ a,
                                                   const float* __restrict__ b,
                                                   const float* __restrict__ wq,
                                                   const float* __restrict__ wk) {
    size_t i = (size_t)(blockIdx.x * 256 + threadIdx.x) * 8;
    float4 a0 = *(const float4*)(a + i), a1 = *(const float4*)(a + i + 4);
    float4 b0 = *(const float4*)(b + i), b1 = *(const float4*)(b + i + 4);
    __half2 p0 = __floats2half2_rn(a0.x + b0.x, a0.y + b0.y);
    __half2 p1 = __floats2half2_rn(a0.z + b0.z, a0.w + b0.w);
    __half2 p2 = __floats2half2_rn(a1.x + b1.x, a1.y + b1.y);
    __half2 p3 = __floats2half2_rn(a1.z + b1.z, a1.w + b1.w);
    uint4 u;
    u.x = *(unsigned*)&p0; u.y = *(unsigned*)&p1;
    u.z = *(unsigned*)&p2; u.w = *(unsigned*)&p3;
    *(uint4*)(g_Xh + i) = u;

    int j = blockIdx.x * 256 + threadIdx.x;
    if (j < 2 * DD * DD) {
        int m = j >> 16, n = (j >> 8) & 255, k = j & 255;
        const float* w = (m == 0) ? wq : wk;
        g_Wt[j] = __float2half_rn(w[k * DD + n]);
    }
}

// ---------------------------------------------------------------------------
// Q,K projections: grid (4, 512); ct = mat*2 + colhalf.
__global__ void __launch_bounds__(256) qk_proj_kernel() {
    extern __shared__ char dsm[];
    int tid = threadIdx.x, wid = tid >> 5, lane = tid & 31;
    int ct = blockIdx.x, mt = blockIdx.y;

    float acc[4][4][4];
    gemm_tile(g_Xh + (size_t)mt * 128 * DD, g_Wt + (size_t)ct * 128 * DD,
              dsm, tid, acc);

    int wm = wid >> 2, wn = wid & 3;
    int lr = lane >> 2, lc = (lane & 3) * 2;
    int mat = ct >> 1;
    int colbase = (ct & 1) * 128;
    const float QSCALE = 0.09016844f;  // (1/16)*log2(e)
    float sc = (mat == 0) ? QSCALE : 1.0f;
    __half* O = (mat == 0) ? g_Qh : g_Kh;

#pragma unroll
    for (int mf = 0; mf < 4; mf++) {
        size_t r0 = (size_t)mt * 128 + wm * 64 + mf * 16 + lr;
        size_t r1 = r0 + 8;
#pragma unroll
        for (int nf = 0; nf < 4; nf++) {
            int c = colbase + wn * 32 + nf * 8 + lc;
            __half2 v0 = __floats2half2_rn(acc[mf][nf][0] * sc, acc[mf][nf][1] * sc);
            __half2 v1 = __floats2half2_rn(acc[mf][nf][2] * sc, acc[mf][nf][3] * sc);
            *(__half2*)(O + r0 * DD + c) = v0;
            *(__half2*)(O + r1 * DD + c) = v1;
        }
    }
}

// ---------------------------------------------------------------------------
// Qs K^T -> exp2 -> P (fp16) + Z rowsum.  grid (16 nt, 16 qt, 32 b).
__global__ void __launch_bounds__(256) qk_mma_kernel() {
    extern __shared__ char dsm[];
    int tid = threadIdx.x, wid = tid >> 5, lane = tid & 31;
    int nt = blockIdx.x, qt = blockIdx.y, b = blockIdx.z;

    float acc[4][4][4];
    gemm_tile(g_Qh + ((size_t)b * NN + qt * 128) * DD,
              g_Kh + ((size_t)b * NN + nt * 128) * DD, dsm, tid, acc);

    int wm = wid >> 2, wn = wid & 3;
    int lr = lane >> 2, lc = (lane & 3) * 2;

#pragma unroll
    for (int mf = 0; mf < 4; mf++) {
        int q0 = qt * 128 + wm * 64 + mf * 16 + lr;
        int q1 = q0 + 8;
        float z0 = 0.0f, z1 = 0.0f;
#pragma unroll
        for (int nf = 0; nf < 4; nf++) {
            int c = nt * 128 + wn * 32 + nf * 8 + lc;
            __half2 p0 = h2exp2(__floats2half2_rn(acc[mf][nf][0], acc[mf][nf][1]));
            __half2 p1 = h2exp2(__floats2half2_rn(acc[mf][nf][2], acc[mf][nf][3]));
            *(__half2*)(g_P + ((size_t)b * NN + q0) * NN + c) = p0;
            *(__half2*)(g_P + ((size_t)b * NN + q1) * NN + c) = p1;
            float2 f0 = __half22float2(p0), f1 = __half22float2(p1);
            z0 += f0.x + f0.y;
            z1 += f1.x + f1.y;
        }
        z0 += __shfl_xor_sync(0xffffffffu, z0, 1);
        z0 += __shfl_xor_sync(0xffffffffu, z0, 2);
        z1 += __shfl_xor_sync(0xffffffffu, z1, 1);
        z1 += __shfl_xor_sync(0xffffffffu, z1, 2);
        if ((lane & 3) == 0) {
            atomicAdd(&g_Z[b * NN + q0], z0);
            atomicAdd(&g_Z[b * NN + q1], z1);
        }
    }
}

// ---------------------------------------------------------------------------
// w_n += sum over 128-q chunk of P/Z.  grid (16, 32); thread owns 8 n (uint4).
__global__ void __launch_bounds__(256) colsum_kernel() {
    __shared__ float rz[128];
    int b = blockIdx.y;
    int q0 = blockIdx.x * 128;
    int tid = threadIdx.x;

    if (tid < 128) rz[tid] = 1.0f / g_Z[b * NN + q0 + tid];
    __syncthreads();

    int n0 = tid * 8;
    float w[8];
#pragma unroll
    for (int j = 0; j < 8; j++) w[j] = 0.0f;

    const __half* Pb = g_P + ((size_t)b * NN + q0) * NN + n0;
#pragma unroll 4
    for (int q = 0; q < 128; q++) {
        uint4 u = *(const uint4*)(Pb + (size_t)q * NN);
        float rzq = rz[q];
        const __half2* h = (const __half2*)&u;
#pragma unroll
        for (int j = 0; j < 4; j++) {
            float2 f = __half22float2(h[j]);
            w[2 * j]     += f.x * rzq;
            w[2 * j + 1] += f.y * rzq;
        }
    }
#pragma unroll
    for (int j = 0; j < 8; j++)
        atomicAdd(&g_Wc[b * NN + n0 + j], w[j]);
}

// ---------------------------------------------------------------------------
// y[b,d] += sum_n w_n * Xh[b,n,d] (fp16 X).  grid (8, 32), 256 thr.
// Two 128-thread groups: group g = tid>>7 covers n-rows [n0+g*128, +128);
// d2 = tid&127 spans the 128 half2 columns (DD=256 halves).
__global__ void __launch_bounds__(256) y_kernel() {
    __shared__ float ws[256];
    int b = blockIdx.y;
    int n0 = blockIdx.x * 256;
    ws[threadIdx.x] = g_Wc[b * NN + n0 + threadIdx.x];
    __syncthreads();

    int g  = threadIdx.x >> 7;             // 0 or 1
    int d2 = threadIdx.x & 127;            // half2 column
    const __half2* Xp =
        (const __half2*)(g_Xh + ((size_t)b * NN + n0 + g * 128) * DD) + d2;
    const float* wsp = ws + g * 128;
    float acc0 = 0.0f, acc1 = 0.0f;
#pragma unroll 8
    for (int r = 0; r < 128; r++) {
        float2 f = __half22float2(Xp[(size_t)r * (DD / 2)]);
        float wr = wsp[r];
        acc0 += wr * f.x;
        acc1 += wr * f.y;
    }
    atomicAdd(&g_Y[b * DD + 2 * d2], acc0);
    atomicAdd(&g_Y[b * DD + 2 * d2 + 1], acc1);
}

// ---------------------------------------------------------------------------
// out[b,k] = sum_d y[b,d] * wv[d,k].  grid 32, fp32 exact.
__global__ void __launch_bounds__(256) out_kernel(const float* __restrict__ wv,
                                                  float* __restrict__ out) {
    __shared__ float ys[DD];
    int b = blockIdx.x, k = threadIdx.x;
    ys[k] = g_Y[b * DD + k];
    __syncthreads();
    float acc = 0.0f;
#pragma unroll 8
    for (int d = 0; d < DD; d++)
        acc += ys[d] * wv[d * DD + k];
    out[b * DD + k] = acc;
}

// ---------------------------------------------------------------------------
extern "C" void kernel_launch(void* const* d_in, const int* in_sizes, int n_in,
                              void* d_out, int out_size) {
    const float* td = (const float*)d_in[0];
    const float* ue = (const float*)d_in[1];
    const float* wq = (const float*)d_in[2];
    const float* wk = (const float*)d_in[3];
    const float* wv = (const float*)d_in[4];
    float* out = (float*)d_out;

    cudaFuncSetAttribute(qk_proj_kernel,
                         cudaFuncAttributeMaxDynamicSharedMemorySize, SMEM_DYN);
    cudaFuncSetAttribute(qk_mma_kernel,
                         cudaFuncAttributeMaxDynamicSharedMemorySize, SMEM_DYN);

    init_kernel<<<(BB * NN) / 256, 256>>>();
    prep_kernel<<<(size_t)BB * NN * DD / (256 * 8), 256>>>(td, ue, wq, wk);
    qk_proj_kernel<<<dim3(4, (BB * NN) / 128), 256, SMEM_DYN>>>();
    qk_mma_kernel<<<dim3(NN / 128, NN / 128, BB), 256, SMEM_DYN>>>();  // 4th: profiled
    colsum_kernel<<<dim3(NN / 128, BB), 256>>>();
    y_kernel<<<dim3(8, BB), 256>>>();
    out_kernel<<<BB, 256>>>(wv, out);
}

// round 14
// speedup vs baseline: 1.1094x; 1.0153x over previous
#include <cuda_runtime.h>
#include <cuda_fp16.h>
#include <cstdint>

// SelfAttention_82403242541160 — R14 (= R13 resubmit after infra flake):
// R12 + tail optimization (colsum streaming+parallelism, P st.cs, init merged).
// out_b = (sum_n w_n x_n) @ Wv,  w_n = sum_q P_qn/Z_q,
// P = exp2(Qs K^T) with (1/16)*log2e folded into Qs, Z = rowsum(P).

#define BB 32
#define NN 2048
#define DD 256

__device__ __half g_Xh[(size_t)BB * NN * DD];
__device__ __half g_Wt[2 * DD * DD];            // Wq^T, Wk^T fp16 [512][256]
__device__ __half g_Qh[(size_t)BB * NN * DD];
__device__ __half g_Kh[(size_t)BB * NN * DD];
__device__ __half g_P [(size_t)BB * NN * NN];   // 256 MB fp16
__device__ float g_Z [BB * NN];
__device__ float g_Wc[BB * NN];
__device__ float g_Y [BB * DD];

// ---------------------------------------------------------------------------
__device__ __forceinline__ uint32_t smem_u32(const void* p) {
    uint32_t a;
    asm("{ .reg .u64 t; cvta.to.shared.u64 t, %1; cvt.u32.u64 %0, t; }"
        : "=r"(a) : "l"(p));
    return a;
}
__device__ __forceinline__ void cp16(uint32_t s, const void* g) {
    asm volatile("cp.async.cg.shared.global [%0], [%1], 16;" :: "r"(s), "l"(g));
}
#define CP_COMMIT() asm volatile("cp.async.commit_group;" ::: "memory")
#define CP_WAIT(n)  asm volatile("cp.async.wait_group %0;" :: "n"(n) : "memory")

__device__ __forceinline__ void ldm_x4(uint32_t addr, uint32_t* r) {
    asm volatile("ldmatrix.sync.aligned.m8n8.x4.shared.b16 {%0,%1,%2,%3}, [%4];"
                 : "=r"(r[0]), "=r"(r[1]), "=r"(r[2]), "=r"(r[3]) : "r"(addr));
}
__device__ __forceinline__ void mma_16816(float* d, const uint32_t* a, const uint32_t* b) {
    asm volatile(
        "mma.sync.aligned.m16n8k16.row.col.f32.f16.f16.f32 "
        "{%0,%1,%2,%3}, {%4,%5,%6,%7}, {%8,%9}, {%0,%1,%2,%3};"
        : "+f"(d[0]), "+f"(d[1]), "+f"(d[2]), "+f"(d[3])
        : "r"(a[0]), "r"(a[1]), "r"(a[2]), "r"(a[3]), "r"(b[0]), "r"(b[1]));
}
// streaming (evict-first) memory ops
__device__ __forceinline__ void stcs32(void* p, uint32_t v) {
    asm volatile("st.global.cs.u32 [%0], %1;" :: "l"(p), "r"(v));
}
__device__ __forceinline__ uint4 ldcs128(const void* p) {
    uint4 v;
    asm volatile("ld.global.cs.v4.u32 {%0,%1,%2,%3}, [%4];"
                 : "=r"(v.x), "=r"(v.y), "=r"(v.z), "=r"(v.w) : "l"(p));
    return v;
}
__device__ __forceinline__ uint32_t ldcs32(const void* p) {
    uint32_t v;
    asm volatile("ld.global.cs.u32 %0, [%1];" : "=r"(v) : "l"(p));
    return v;
}

// smem stage: A(128x64h) + B(128x64h), 128 B/row, 16B units swizzled u ^= (row&7)
#define STAGE_BYTES 32768
#define SMEM_DYN    (3 * STAGE_BYTES)

__device__ __forceinline__ void load_stage(
    uint32_t st, const __half* __restrict__ Ag, const __half* __restrict__ Bg,
    int k0, int tid) {
#pragma unroll
    for (int i = 0; i < 4; i++) {
        int u_idx = tid + i * 256;            // 0..1023
        int row = u_idx >> 3, u = u_idx & 7;
        uint32_t so = (uint32_t)((row << 7) + ((u ^ (row & 7)) << 4));
        cp16(st + so, Ag + (size_t)row * DD + k0 + u * 8);
        cp16(st + 16384 + so, Bg + (size_t)row * DD + k0 + u * 8);
    }
}

// Warp grid 2x4 (proven config): warp tile 64x32, acc[4][4][4].
__device__ __forceinline__ void compute_stage(
    uint32_t smA, uint32_t smB, int wm, int wn, int lane, float acc[4][4][4]) {
    int arow = wm * 64 + (lane & 15);
    int ahalf = lane >> 4;
    int brow = wn * 32 + ((lane >> 4) << 3) + (lane & 7);
    int bhalf = (lane >> 3) & 1;
#pragma unroll
    for (int ks = 0; ks < 4; ks++) {
        uint32_t a[4][4];
#pragma unroll
        for (int mf = 0; mf < 4; mf++) {
            int r = arow + mf * 16;
            int u = ks * 2 + ahalf;
            ldm_x4(smA + (r << 7) + ((u ^ (r & 7)) << 4), a[mf]);
        }
        uint32_t b[4][2];
#pragma unroll
        for (int p = 0; p < 2; p++) {
            int r = brow + p * 16;
            int u = ks * 2 + bhalf;
            uint32_t t[4];
            ldm_x4(smB + (r << 7) + ((u ^ (r & 7)) << 4), t);
            b[p * 2][0] = t[0];     b[p * 2][1] = t[1];
            b[p * 2 + 1][0] = t[2]; b[p * 2 + 1][1] = t[3];
        }
#pragma unroll
        for (int mf = 0; mf < 4; mf++)
#pragma unroll
            for (int nf = 0; nf < 4; nf++)
                mma_16816(acc[mf][nf], a[mf], b[nf]);
    }
}

// 128x128x256 tile GEMM, 3-buffer pipeline, one syncthreads per K-chunk.
__device__ __forceinline__ void gemm_tile(
    const __half* __restrict__ Ag, const __half* __restrict__ Bg,
    char* dsm, int tid, float acc[4][4][4]) {
    uint32_t sm0 = smem_u32(dsm);
    int wid = tid >> 5, lane = tid & 31;
    int wm = wid >> 2, wn = wid & 3;

#pragma unroll
    for (int mf = 0; mf < 4; mf++)
#pragma unroll
        for (int nf = 0; nf < 4; nf++)
#pragma unroll
            for (int j = 0; j < 4; j++) acc[mf][nf][j] = 0.0f;

    load_stage(sm0, Ag, Bg, 0, tid);
    CP_COMMIT();
    load_stage(sm0 + STAGE_BYTES, Ag, Bg, 64, tid);
    CP_COMMIT();

#pragma unroll
    for (int it = 0; it < 4; it++) {
        if (it < 3) { CP_WAIT(1); } else { CP_WAIT(0); }
        __syncthreads();
        if (it < 2) {
            load_stage(sm0 + ((it + 2) % 3) * STAGE_BYTES, Ag, Bg, (it + 2) * 64, tid);
            CP_COMMIT();
        }
        uint32_t cs = sm0 + (it % 3) * STAGE_BYTES;
        compute_stage(cs, cs + 16384, wm, wn, lane, acc);
    }
}

// ---------------------------------------------------------------------------
// prep: X = td+ue (fp16); Wt transpose on first 512 blocks; Z/Wc/Y zero on
// first 256 blocks.  grid 8192.
__global__ void __launch_bounds__(256) prep_kernel(const float* __restrict__ a,
                                                   const float* __restrict__ b,
                                                   const float* __restrict__ wq,
                                                   const float* __restrict__ wk) {
    size_t i = (size_t)(blockIdx.x * 256 + threadIdx.x) * 8;
    float4 a0 = *(const float4*)(a + i), a1 = *(const float4*)(a + i + 4);
    float4 b0 = *(const float4*)(b + i), b1 = *(const float4*)(b + i + 4);
    __half2 p0 = __floats2half2_rn(a0.x + b0.x, a0.y + b0.y);
    __half2 p1 = __floats2half2_rn(a0.z + b0.z, a0.w + b0.w);
    __half2 p2 = __floats2half2_rn(a1.x + b1.x, a1.y + b1.y);
    __half2 p3 = __floats2half2_rn(a1.z + b1.z, a1.w + b1.w);
    uint4 u;
    u.x = *(unsigned*)&p0; u.y = *(unsigned*)&p1;
    u.z = *(unsigned*)&p2; u.w = *(unsigned*)&p3;
    *(uint4*)(g_Xh + i) = u;

    int j = blockIdx.x * 256 + threadIdx.x;
    if (j < 2 * DD * DD) {
        int m = j >> 16, n = (j >> 8) & 255, k = j & 255;
        const float* w = (m == 0) ? wq : wk;
        g_Wt[j] = __float2half_rn(w[k * DD + n]);
    }
    if (j < BB * NN) { g_Z[j] = 0.0f; g_Wc[j] = 0.0f; }
    if (j < BB * DD) g_Y[j] = 0.0f;
}

// ---------------------------------------------------------------------------
// Q,K projections: grid (4, 512); ct = mat*2 + colhalf.
__global__ void __launch_bounds__(256) qk_proj_kernel() {
    extern __shared__ char dsm[];
    int tid = threadIdx.x, wid = tid >> 5, lane = tid & 31;
    int ct = blockIdx.x, mt = blockIdx.y;

    float acc[4][4][4];
    gemm_tile(g_Xh + (size_t)mt * 128 * DD, g_Wt + (size_t)ct * 128 * DD,
              dsm, tid, acc);

    int wm = wid >> 2, wn = wid & 3;
    int lr = lane >> 2, lc = (lane & 3) * 2;
    int mat = ct >> 1;
    int colbase = (ct & 1) * 128;
    const float QSCALE = 0.09016844f;  // (1/16)*log2(e)
    float sc = (mat == 0) ? QSCALE : 1.0f;
    __half* O = (mat == 0) ? g_Qh : g_Kh;

#pragma unroll
    for (int mf = 0; mf < 4; mf++) {
        size_t r0 = (size_t)mt * 128 + wm * 64 + mf * 16 + lr;
        size_t r1 = r0 + 8;
#pragma unroll
        for (int nf = 0; nf < 4; nf++) {
            int c = colbase + wn * 32 + nf * 8 + lc;
            __half2 v0 = __floats2half2_rn(acc[mf][nf][0] * sc, acc[mf][nf][1] * sc);
            __half2 v1 = __floats2half2_rn(acc[mf][nf][2] * sc, acc[mf][nf][3] * sc);
            *(__half2*)(O + r0 * DD + c) = v0;
            *(__half2*)(O + r1 * DD + c) = v1;
        }
    }
}

// ---------------------------------------------------------------------------
// Qs K^T -> exp2 -> P (fp16, streaming store) + Z rowsum.  grid (16,16,32).
__global__ void __launch_bounds__(256) qk_mma_kernel() {
    extern __shared__ char dsm[];
    int tid = threadIdx.x, wid = tid >> 5, lane = tid & 31;
    int nt = blockIdx.x, qt = blockIdx.y, b = blockIdx.z;

    float acc[4][4][4];
    gemm_tile(g_Qh + ((size_t)b * NN + qt * 128) * DD,
              g_Kh + ((size_t)b * NN + nt * 128) * DD, dsm, tid, acc);

    int wm = wid >> 2, wn = wid & 3;
    int lr = lane >> 2, lc = (lane & 3) * 2;

#pragma unroll
    for (int mf = 0; mf < 4; mf++) {
        int q0 = qt * 128 + wm * 64 + mf * 16 + lr;
        int q1 = q0 + 8;
        float z0 = 0.0f, z1 = 0.0f;
#pragma unroll
        for (int nf = 0; nf < 4; nf++) {
            int c = nt * 128 + wn * 32 + nf * 8 + lc;
            __half2 p0 = h2exp2(__floats2half2_rn(acc[mf][nf][0], acc[mf][nf][1]));
            __half2 p1 = h2exp2(__floats2half2_rn(acc[mf][nf][2], acc[mf][nf][3]));
            stcs32(g_P + ((size_t)b * NN + q0) * NN + c, *(uint32_t*)&p0);
            stcs32(g_P + ((size_t)b * NN + q1) * NN + c, *(uint32_t*)&p1);
            float2 f0 = __half22float2(p0), f1 = __half22float2(p1);
            z0 += f0.x + f0.y;
            z1 += f1.x + f1.y;
        }
        z0 += __shfl_xor_sync(0xffffffffu, z0, 1);
        z0 += __shfl_xor_sync(0xffffffffu, z0, 2);
        z1 += __shfl_xor_sync(0xffffffffu, z1, 1);
        z1 += __shfl_xor_sync(0xffffffffu, z1, 2);
        if ((lane & 3) == 0) {
            atomicAdd(&g_Z[b * NN + q0], z0);
            atomicAdd(&g_Z[b * NN + q1], z1);
        }
    }
}

// ---------------------------------------------------------------------------
// w_n += sum over 64-q chunk of P/Z.  grid (32, 32) = 1024 blocks;
// thread owns 8 n (uint4, streaming loads), unroll 8 over 64 rows.
__global__ void __launch_bounds__(256) colsum_kernel() {
    __shared__ float rz[64];
    int b = blockIdx.y;
    int q0 = blockIdx.x * 64;
    int tid = threadIdx.x;

    if (tid < 64) rz[tid] = 1.0f / g_Z[b * NN + q0 + tid];
    __syncthreads();

    int n0 = tid * 8;
    float w[8];
#pragma unroll
    for (int j = 0; j < 8; j++) w[j] = 0.0f;

    const __half* Pb = g_P + ((size_t)b * NN + q0) * NN + n0;
#pragma unroll 8
    for (int q = 0; q < 64; q++) {
        uint4 u = ldcs128(Pb + (size_t)q * NN);
        float rzq = rz[q];
        const __half2* h = (const __half2*)&u;
#pragma unroll
        for (int j = 0; j < 4; j++) {
            float2 f = __half22float2(h[j]);
            w[2 * j]     += f.x * rzq;
            w[2 * j + 1] += f.y * rzq;
        }
    }
#pragma unroll
    for (int j = 0; j < 8; j++)
        atomicAdd(&g_Wc[b * NN + n0 + j], w[j]);
}

// ---------------------------------------------------------------------------
// y[b,d] += sum_n w_n * Xh[b,n,d] (fp16 X, streaming).  grid (8, 32), 256 thr.
// Two 128-thread groups: group g covers 128 n-rows; d2 spans 128 half2 cols.
__global__ void __launch_bounds__(256) y_kernel() {
    __shared__ float ws[256];
    int b = blockIdx.y;
    int n0 = blockIdx.x * 256;
    ws[threadIdx.x] = g_Wc[b * NN + n0 + threadIdx.x];
    __syncthreads();

    int g  = threadIdx.x >> 7;
    int d2 = threadIdx.x & 127;
    const __half2* Xp =
        (const __half2*)(g_Xh + ((size_t)b * NN + n0 + g * 128) * DD) + d2;
    const float* wsp = ws + g * 128;
    float acc0 = 0.0f, acc1 = 0.0f;
#pragma unroll 8
    for (int r = 0; r < 128; r++) {
        uint32_t raw = ldcs32(Xp + (size_t)r * (DD / 2));
        float2 f = __half22float2(*(__half2*)&raw);
        float wr = wsp[r];
        acc0 += wr * f.x;
        acc1 += wr * f.y;
    }
    atomicAdd(&g_Y[b * DD + 2 * d2], acc0);
    atomicAdd(&g_Y[b * DD + 2 * d2 + 1], acc1);
}

// ---------------------------------------------------------------------------
// out[b,k] = sum_d y[b,d] * wv[d,k].  grid 32, fp32 exact.
__global__ void __launch_bounds__(256) out_kernel(const float* __restrict__ wv,
                                                  float* __restrict__ out) {
    __shared__ float ys[DD];
    int b = blockIdx.x, k = threadIdx.x;
    ys[k] = g_Y[b * DD + k];
    __syncthreads();
    float acc = 0.0f;
#pragma unroll 8
    for (int d = 0; d < DD; d++)
        acc += ys[d] * wv[d * DD + k];
    out[b * DD + k] = acc;
}

// ---------------------------------------------------------------------------
extern "C" void kernel_launch(void* const* d_in, const int* in_sizes, int n_in,
                              void* d_out, int out_size) {
    const float* td = (const float*)d_in[0];
    const float* ue = (const float*)d_in[1];
    const float* wq = (const float*)d_in[2];
    const float* wk = (const float*)d_in[3];
    const float* wv = (const float*)d_in[4];
    float* out = (float*)d_out;

    cudaFuncSetAttribute(qk_proj_kernel,
                         cudaFuncAttributeMaxDynamicSharedMemorySize, SMEM_DYN);
    cudaFuncSetAttribute(qk_mma_kernel,
                         cudaFuncAttributeMaxDynamicSharedMemorySize, SMEM_DYN);

    prep_kernel<<<(size_t)BB * NN * DD / (256 * 8), 256>>>(td, ue, wq, wk);
    qk_proj_kernel<<<dim3(4, (BB * NN) / 128), 256, SMEM_DYN>>>();
    qk_mma_kernel<<<dim3(NN / 128, NN / 128, BB), 256, SMEM_DYN>>>();
    colsum_kernel<<<dim3(NN / 64, BB), 256>>>();   // 4th launch: profiled
    y_kernel<<<dim3(8, BB), 256>>>();
    out_kernel<<<BB, 256>>>(wv, out);
}